// round 3
// baseline (speedup 1.0000x reference)
#include <cuda_runtime.h>
#include <cuda_bf16.h>
#include <cstdint>
#include <math.h>

using bf16 = __nv_bfloat16;

#define TT 64
#define BB 64
#define EE 512
#define HH 1024
#define SS 128
#define VV 1024

// ---- persistent scratch (device globals; no allocation) ----
__device__ __align__(16) bf16 g_Whi[2][2048u*4096u];  // LSTM weights, k-major [k][n]
__device__ __align__(16) bf16 g_Wlo[2][2048u*4096u];
__device__ __align__(16) bf16 g_W1hi[1024u*1024u];
__device__ __align__(16) bf16 g_W1lo[1024u*1024u];
__device__ __align__(16) bf16 g_W2hi[2048u*512u];
__device__ __align__(16) bf16 g_W2lo[2048u*512u];
__device__ __align__(16) bf16 g_a0hi[(size_t)TT*BB*2048];  // per-t layer0 input [x|out|h0]
__device__ __align__(16) bf16 g_a0lo[(size_t)TT*BB*2048];
__device__ __align__(16) bf16 g_a1hi[BB*2048];             // layer1 input [h0|h1prev]
__device__ __align__(16) bf16 g_a1lo[BB*2048];
__device__ __align__(16) bf16 g_aqhi[BB*1024];             // h1 for W1 gemm
__device__ __align__(16) bf16 g_aqlo[BB*1024];
__device__ __align__(16) bf16 g_aohi[BB*2048];             // [attended|h1]
__device__ __align__(16) bf16 g_aolo[BB*2048];
__device__ float g_gP[2][BB*4096];   // split-K partials (LSTM gates)
__device__ float g_qP[4][BB*1024];
__device__ float g_oP[8][BB*512];
__device__ float g_c[2][BB*1024];    // cell states

// ---- helpers ----
__device__ __forceinline__ void splitbf(float x, bf16* h, bf16* l) {
    bf16 hi = __float2bfloat16(x);
    *h = hi;
    *l = __float2bfloat16(x - __bfloat162float(hi));
}

__device__ __forceinline__ void cp16(bf16* s, const bf16* g) {
    uint32_t sa = (uint32_t)__cvta_generic_to_shared(s);
    asm volatile("cp.async.cg.shared.global [%0], [%1], 16;" :: "r"(sa), "l"(g) : "memory");
}

// ---- generic split-bf16 GEMM: C[64,N] = Ahi@Bhi + Alo@Bhi + Ahi@Blo ----
// A row-major [64][K] (lda), B k-major [K][N] (ldb). grid(N/64, splitK).
// Cp layout: [splitK][64][N].
__global__ __launch_bounds__(256, 2) void gemm_split3(
    const bf16* __restrict__ Ahi, const bf16* __restrict__ Alo, int lda,
    const bf16* __restrict__ Bhi, const bf16* __restrict__ Blo, int ldb,
    float* __restrict__ Cp, int N, int Ksplit)
{
    __shared__ bf16 As[2][64][64];
    __shared__ bf16 Bs[2][64][64];
    const int tid = threadIdx.x, lane = tid & 31, wp = tid >> 5;
    const int wm = wp >> 2, wn = wp & 3;
    const int nb = blockIdx.x * 64;
    const int k0 = blockIdx.y * Ksplit;
    const int nk = Ksplit >> 6;
    const int iters = 3 * nk;
    const bf16* At[3] = {Ahi, Alo, Ahi};
    const bf16* Bt[3] = {Bhi, Bhi, Blo};

    float acc[2][2][4];
#pragma unroll
    for (int i = 0; i < 2; i++)
#pragma unroll
        for (int j = 0; j < 2; j++)
#pragma unroll
            for (int r = 0; r < 4; r++) acc[i][j][r] = 0.f;

    auto issue = [&](int it, int buf) {
        int term = it / nk;
        int kb = k0 + (it - term * nk) * 64;
        const bf16* Ag = At[term];
        const bf16* Bg = Bt[term];
#pragma unroll
        for (int r = 0; r < 2; r++) {
            int ch = tid + 256 * r, row = ch >> 3, c8 = ch & 7;
            cp16(&As[buf][row][((c8 ^ (row & 7)) << 3)], Ag + (size_t)row * lda + kb + (c8 << 3));
            cp16(&Bs[buf][row][((c8 ^ (row & 7)) << 3)], Bg + (size_t)(kb + row) * ldb + nb + (c8 << 3));
        }
        asm volatile("cp.async.commit_group;");
    };

    issue(0, 0);
    for (int it = 0; it < iters; ++it) {
        int buf = it & 1;
        if (it + 1 < iters) {
            issue(it + 1, buf ^ 1);
            asm volatile("cp.async.wait_group 1;");
        } else {
            asm volatile("cp.async.wait_group 0;");
        }
        __syncthreads();
#pragma unroll
        for (int kk = 0; kk < 4; kk++) {
            uint32_t a[2][4], b[2][2];
#pragma unroll
            for (int mi = 0; mi < 2; mi++) {
                int m = (wm << 5) + (mi << 4) + (lane & 15);
                int pc = ((kk << 1) + (lane >> 4)) ^ (m & 7);
                uint32_t ad = (uint32_t)__cvta_generic_to_shared(&As[buf][m][pc << 3]);
                asm volatile("ldmatrix.sync.aligned.m8n8.x4.shared.b16 {%0,%1,%2,%3},[%4];"
                             : "=r"(a[mi][0]), "=r"(a[mi][1]), "=r"(a[mi][2]), "=r"(a[mi][3]) : "r"(ad));
            }
#pragma unroll
            for (int ni = 0; ni < 2; ni++) {
                int kr = (kk << 4) + (lane & 15);
                int pc = ((wn << 1) + ni) ^ (kr & 7);
                uint32_t ad = (uint32_t)__cvta_generic_to_shared(&Bs[buf][kr][pc << 3]);
                asm volatile("ldmatrix.sync.aligned.m8n8.x2.trans.shared.b16 {%0,%1},[%2];"
                             : "=r"(b[ni][0]), "=r"(b[ni][1]) : "r"(ad));
            }
#pragma unroll
            for (int mi = 0; mi < 2; mi++)
#pragma unroll
                for (int ni = 0; ni < 2; ni++)
                    asm volatile(
                        "mma.sync.aligned.m16n8k16.row.col.f32.bf16.bf16.f32 "
                        "{%0,%1,%2,%3},{%4,%5,%6,%7},{%8,%9},{%0,%1,%2,%3};"
                        : "+f"(acc[mi][ni][0]), "+f"(acc[mi][ni][1]), "+f"(acc[mi][ni][2]), "+f"(acc[mi][ni][3])
                        : "r"(a[mi][0]), "r"(a[mi][1]), "r"(a[mi][2]), "r"(a[mi][3]),
                          "r"(b[ni][0]), "r"(b[ni][1]));
        }
        __syncthreads();
    }

    float* C = Cp + (size_t)blockIdx.y * 64 * N;
#pragma unroll
    for (int mi = 0; mi < 2; mi++)
#pragma unroll
        for (int ni = 0; ni < 2; ni++) {
            int row = (wm << 5) + (mi << 4) + (lane >> 2);
            int col = nb + (wn << 4) + (ni << 3) + ((lane & 3) << 1);
            C[(size_t)row * N + col]           = acc[mi][ni][0];
            C[(size_t)row * N + col + 1]       = acc[mi][ni][1];
            C[(size_t)(row + 8) * N + col]     = acc[mi][ni][2];
            C[(size_t)(row + 8) * N + col + 1] = acc[mi][ni][3];
        }
}

// ---- LSTM cell: combine splitK partials + biases, update c, write split h ----
__global__ void cell_k(const float* __restrict__ g0, const float* __restrict__ g1,
                       const float* __restrict__ bih, const float* __restrict__ bhh,
                       float* __restrict__ c,
                       bf16* d0h, bf16* d0l, int s0,
                       bf16* d1h, bf16* d1l, int s1,
                       bf16* d2h, bf16* d2l, int s2)
{
    int idx = blockIdx.x * blockDim.x + threadIdx.x;  // 64*1024
    int b = idx >> 10, j = idx & 1023;
    const float* p0 = g0 + (size_t)b * 4096;
    const float* p1 = g1 + (size_t)b * 4096;
    float gi = p0[j]        + p1[j]        + bih[j]        + bhh[j];
    float gf = p0[1024 + j] + p1[1024 + j] + bih[1024 + j] + bhh[1024 + j];
    float gg = p0[2048 + j] + p1[2048 + j] + bih[2048 + j] + bhh[2048 + j];
    float go = p0[3072 + j] + p1[3072 + j] + bih[3072 + j] + bhh[3072 + j];
    float si = 1.f / (1.f + expf(-gi));
    float sf = 1.f / (1.f + expf(-gf));
    float so = 1.f / (1.f + expf(-go));
    float cn = sf * c[idx] + si * tanhf(gg);
    c[idx] = cn;
    float h = so * tanhf(cn);
    bf16 hi, lo;
    splitbf(h, &hi, &lo);
    if (d0h) { d0h[(size_t)b * s0 + j] = hi; d0l[(size_t)b * s0 + j] = lo; }
    if (d1h) { d1h[(size_t)b * s1 + j] = hi; d1l[(size_t)b * s1 + j] = lo; }
    if (d2h) { d2h[(size_t)b * s2 + j] = hi; d2l[(size_t)b * s2 + j] = lo; }
}

// ---- attention: combine qP + b1, scores, softmax, attended -> ao slot0 ----
__global__ __launch_bounds__(512) void attn_k(const float* __restrict__ qP,
                                              const float* __restrict__ b1,
                                              const float* __restrict__ enc,
                                              bf16* __restrict__ aoh, bf16* __restrict__ aol)
{
    __shared__ float qs[1024];
    __shared__ float sc[128];
    int b = blockIdx.x, tid = threadIdx.x, lane = tid & 31, wp = tid >> 5;
    for (int v = tid; v < 1024; v += 512) {
        float s = b1[v];
#pragma unroll
        for (int p = 0; p < 4; p++) s += qP[(size_t)p * BB * 1024 + (size_t)b * 1024 + v];
        qs[v] = s;
    }
    __syncthreads();
    const float* eb = enc + (size_t)b * SS * VV;
    for (int s = wp; s < SS; s += 16) {
        const float* e = eb + (size_t)s * VV;
        float acc = 0.f;
        for (int k = lane; k < VV; k += 32) acc += qs[k] * e[k];
#pragma unroll
        for (int o = 16; o > 0; o >>= 1) acc += __shfl_xor_sync(0xffffffffu, acc, o);
        if (lane == 0) sc[s] = acc;
    }
    __syncthreads();
    if (wp == 0) {
        float m = -1e30f;
#pragma unroll
        for (int i = 0; i < 4; i++) m = fmaxf(m, sc[lane + 32 * i]);
#pragma unroll
        for (int o = 16; o > 0; o >>= 1) m = fmaxf(m, __shfl_xor_sync(0xffffffffu, m, o));
        float ex[4], sum = 0.f;
#pragma unroll
        for (int i = 0; i < 4; i++) { ex[i] = expf(sc[lane + 32 * i] - m); sum += ex[i]; }
#pragma unroll
        for (int o = 16; o > 0; o >>= 1) sum += __shfl_xor_sync(0xffffffffu, sum, o);
        float inv = 1.f / sum;
#pragma unroll
        for (int i = 0; i < 4; i++) sc[lane + 32 * i] = ex[i] * inv;
    }
    __syncthreads();
    float a0 = 0.f, a1 = 0.f;
#pragma unroll 4
    for (int s = 0; s < SS; s++) {
        float w = sc[s];
        a0 += w * eb[(size_t)s * VV + tid];
        a1 += w * eb[(size_t)s * VV + tid + 512];
    }
    bf16 hi, lo;
    splitbf(a0, &hi, &lo);
    aoh[(size_t)b * 2048 + tid] = hi; aol[(size_t)b * 2048 + tid] = lo;
    splitbf(a1, &hi, &lo);
    aoh[(size_t)b * 2048 + tid + 512] = hi; aol[(size_t)b * 2048 + tid + 512] = lo;
}

// ---- output: combine oP + b2, tanh, write d_out and input-feed slot ----
__global__ void out_k(const float* __restrict__ oP, const float* __restrict__ b2,
                      float* __restrict__ out, int t, bf16* nxh, bf16* nxl)
{
    int idx = blockIdx.x * blockDim.x + threadIdx.x;  // 64*512
    int b = idx >> 9, e = idx & 511;
    float s = b2[e];
#pragma unroll
    for (int p = 0; p < 8; p++) s += oP[(size_t)p * BB * 512 + idx];
    float o = tanhf(s);
    out[((size_t)b * TT + t) * EE + e] = o;
    if (nxh) {
        bf16 hi, lo;
        splitbf(o, &hi, &lo);
        nxh[(size_t)b * 2048 + e] = hi;
        nxl[(size_t)b * 2048 + e] = lo;
    }
}

// ---- transpose + split fp32 [R][C] -> bf16 hi/lo [C][R] (dst row stride ldd) ----
__global__ void tsplit(const float* __restrict__ src, bf16* __restrict__ dhi,
                       bf16* __restrict__ dlo, int R, int C, int ldd)
{
    __shared__ float t[32][33];
    int kb = blockIdx.x << 5, nbs = blockIdx.y << 5;
    int tx = threadIdx.x, ty = threadIdx.y;  // 32x8
    for (int i = ty; i < 32; i += 8) t[i][tx] = src[(size_t)(nbs + i) * C + kb + tx];
    __syncthreads();
    for (int i = ty; i < 32; i += 8) {
        float v = t[tx][i];
        size_t o = (size_t)(kb + i) * ldd + nbs + tx;
        bf16 hi, lo;
        splitbf(v, &hi, &lo);
        dhi[o] = hi; dlo[o] = lo;
    }
}

// ---- embed all timesteps into a0 x-slot ----
__global__ void embed_k(const int* __restrict__ tgt, const float* __restrict__ emb)
{
    int idx = blockIdx.x * blockDim.x + threadIdx.x;
    if (idx >= TT * BB * EE) return;
    int e = idx & 511, tb = idx >> 9;
    int b = tb & 63, t = tb >> 6;
    int tok = tgt[t * BB + b];
    float v = emb[(size_t)tok * EE + e];
    size_t o = ((size_t)t * BB + b) * 2048 + e;
    bf16 hi, lo;
    splitbf(v, &hi, &lo);
    g_a0hi[o] = hi; g_a0lo[o] = lo;
}

// ---- init: c=0, a1 slot1 = hinit[1], a0[0] h0 slot = hinit[0], a0[0] out slot ----
__global__ void init_k(const float* __restrict__ out0, const float* __restrict__ hinit)
{
    int idx = blockIdx.x * blockDim.x + threadIdx.x;  // 64*1024
    if (idx >= BB * HH) return;
    int b = idx >> 10, j = idx & 1023;
    g_c[0][idx] = 0.f; g_c[1][idx] = 0.f;
    bf16 hi, lo;
    splitbf(hinit[(size_t)BB * HH + idx], &hi, &lo);  // layer1 h init
    g_a1hi[(size_t)b * 2048 + 1024 + j] = hi;
    g_a1lo[(size_t)b * 2048 + 1024 + j] = lo;
    splitbf(hinit[idx], &hi, &lo);                    // layer0 h init
    g_a0hi[(size_t)b * 2048 + 1024 + j] = hi;
    g_a0lo[(size_t)b * 2048 + 1024 + j] = lo;
    if (j < 512) {
        splitbf(out0[(size_t)b * EE + j], &hi, &lo);  // input feed init
        g_a0hi[(size_t)b * 2048 + 512 + j] = hi;
        g_a0lo[(size_t)b * 2048 + 512 + j] = lo;
    }
}

extern "C" void kernel_launch(void* const* d_in, const int* in_sizes, int n_in,
                              void* d_out, int out_size)
{
    const int*   tgt   = (const int*)d_in[0];
    const float* enc   = (const float*)d_in[1];
    const float* emb   = (const float*)d_in[2];
    const float* out0  = (const float*)d_in[3];
    const float* hinit = (const float*)d_in[4];
    const float* Wih   = (const float*)d_in[5];
    const float* Whh   = (const float*)d_in[6];
    const float* bih   = (const float*)d_in[7];
    const float* bhh   = (const float*)d_in[8];
    const float* W1    = (const float*)d_in[9];
    const float* b1    = (const float*)d_in[10];
    const float* W2    = (const float*)d_in[11];
    const float* b2    = (const float*)d_in[12];
    float* out = (float*)d_out;

    bf16 *Whi, *Wlo, *W1h, *W1l, *W2h, *W2l;
    bf16 *a0h, *a0l, *a1h, *a1l, *aqh, *aql, *aoh, *aol;
    float *gP, *qP, *oP, *cst;
    cudaGetSymbolAddress((void**)&Whi, g_Whi);
    cudaGetSymbolAddress((void**)&Wlo, g_Wlo);
    cudaGetSymbolAddress((void**)&W1h, g_W1hi);
    cudaGetSymbolAddress((void**)&W1l, g_W1lo);
    cudaGetSymbolAddress((void**)&W2h, g_W2hi);
    cudaGetSymbolAddress((void**)&W2l, g_W2lo);
    cudaGetSymbolAddress((void**)&a0h, g_a0hi);
    cudaGetSymbolAddress((void**)&a0l, g_a0lo);
    cudaGetSymbolAddress((void**)&a1h, g_a1hi);
    cudaGetSymbolAddress((void**)&a1l, g_a1lo);
    cudaGetSymbolAddress((void**)&aqh, g_aqhi);
    cudaGetSymbolAddress((void**)&aql, g_aqlo);
    cudaGetSymbolAddress((void**)&aoh, g_aohi);
    cudaGetSymbolAddress((void**)&aol, g_aolo);
    cudaGetSymbolAddress((void**)&gP,  g_gP);
    cudaGetSymbolAddress((void**)&qP,  g_qP);
    cudaGetSymbolAddress((void**)&oP,  g_oP);
    cudaGetSymbolAddress((void**)&cst, g_c);

    const size_t LW = (size_t)2048 * 4096;  // per-layer split weight elems
    dim3 tb(32, 8);
    for (int l = 0; l < 2; l++) {
        tsplit<<<dim3(1024 / 32, 4096 / 32), tb>>>(Wih + (size_t)l * 4096 * 1024,
            Whi + l * LW, Wlo + l * LW, 4096, 1024, 4096);
        tsplit<<<dim3(1024 / 32, 4096 / 32), tb>>>(Whh + (size_t)l * 4096 * 1024,
            Whi + l * LW + (size_t)1024 * 4096, Wlo + l * LW + (size_t)1024 * 4096, 4096, 1024, 4096);
    }
    tsplit<<<dim3(32, 32), tb>>>(W1, W1h, W1l, 1024, 1024, 1024);
    tsplit<<<dim3(64, 16), tb>>>(W2, W2h, W2l, 512, 2048, 512);
    embed_k<<<(TT * BB * EE + 255) / 256, 256>>>(tgt, emb);
    init_k<<<(BB * HH + 255) / 256, 256>>>(out0, hinit);

    for (int t = 0; t < TT; t++) {
        const bf16* A0h = a0h + (size_t)t * BB * 2048;
        const bf16* A0l = a0l + (size_t)t * BB * 2048;
        bf16* nxHh = (t + 1 < TT) ? a0h + (size_t)(t + 1) * BB * 2048 + 1024 : nullptr;
        bf16* nxHl = (t + 1 < TT) ? a0l + (size_t)(t + 1) * BB * 2048 + 1024 : nullptr;
        bf16* nxOh = (t + 1 < TT) ? a0h + (size_t)(t + 1) * BB * 2048 + 512 : nullptr;
        bf16* nxOl = (t + 1 < TT) ? a0l + (size_t)(t + 1) * BB * 2048 + 512 : nullptr;

        // layer0 gates
        gemm_split3<<<dim3(64, 2), 256>>>(A0h, A0l, 2048, Whi, Wlo, 4096, gP, 4096, 1024);
        cell_k<<<256, 256>>>(gP, gP + BB * 4096, bih, bhh, cst,
                             a1h, a1l, 2048, nxHh, nxHl, 2048, nullptr, nullptr, 0);
        // layer1 gates
        gemm_split3<<<dim3(64, 2), 256>>>(a1h, a1l, 2048, Whi + LW, Wlo + LW, 4096, gP, 4096, 1024);
        cell_k<<<256, 256>>>(gP, gP + BB * 4096, bih + 4096, bhh + 4096, cst + BB * HH,
                             a1h + 1024, a1l + 1024, 2048, aqh, aql, 1024, aoh + 1024, aol + 1024, 2048);
        // q = h1 @ W1^T (+b1 folded into attn)
        gemm_split3<<<dim3(16, 4), 256>>>(aqh, aql, 1024, W1h, W1l, 1024, qP, 1024, 256);
        attn_k<<<64, 512>>>(qP, b1, enc, aoh, aol);
        // o = tanh([attended|h1] @ W2^T + b2)
        gemm_split3<<<dim3(8, 8), 256>>>(aoh, aol, 2048, W2h, W2l, 512, oP, 512, 256);
        out_k<<<128, 256>>>(oP, b2, out, t, nxOh, nxOl);
    }
}